// round 9
// baseline (speedup 1.0000x reference)
#include <cuda_runtime.h>

// DeconvDft2dLayer == per-row 512-pt circular deconvolution:
//   y[row,:] = ifft( M(k) * fft(x[row,:]) ),  M(k) = 1/|H(k)|^4 (real),
//   H(k) = sum_{n=0}^{7} w[n] e^{-2pi i k n/512}.
// Two real rows packed per complex FFT (M real => exact).
// 512 = 16 x 32: 16 threads/FFT, one smem transpose per direction.
// Inverse via conj trick reuses the forward pipeline. Inter-pass permute is
// staged through the (idle) transpose buffer to cut peak registers.
// M computed once per block (f==0 group) into smem: zero-padded FFT32 of
// w[n]*W^{tn} gives H at bins t+16m. Single kernel launch.

#define NW 512
#define NFB 4                   // FFTs per block (8 rows)
#define THREADS 64
#define SBUF 552                // float2 per FFT region (544 used; 552%16=8 -> f0/f1 bank-disjoint)

__device__ __forceinline__ float2 cmulf(float2 a, float2 b) {
    return make_float2(a.x * b.x - a.y * b.y, a.x * b.y + a.y * b.x);
}

// cos/sin(2*pi*j/32), j = 0..15 (compile-time).
__device__ __forceinline__ constexpr float c32(int j) {
    switch (j) {
        case 0:  return 1.0f;
        case 1:  return 0.9807852804032304491f;
        case 2:  return 0.9238795325112867561f;
        case 3:  return 0.8314696123025452371f;
        case 4:  return 0.7071067811865475244f;
        case 5:  return 0.5555702330196022248f;
        case 6:  return 0.3826834323650897717f;
        case 7:  return 0.1950903220161282678f;
        case 8:  return 0.0f;
        case 9:  return -0.1950903220161282678f;
        case 10: return -0.3826834323650897717f;
        case 11: return -0.5555702330196022248f;
        case 12: return -0.7071067811865475244f;
        case 13: return -0.8314696123025452371f;
        case 14: return -0.9238795325112867561f;
        default: return -0.9807852804032304491f;
    }
}
__device__ __forceinline__ constexpr float s32(int j) {
    switch (j) {
        case 0:  return 0.0f;
        case 1:  return 0.1950903220161282678f;
        case 2:  return 0.3826834323650897717f;
        case 3:  return 0.5555702330196022248f;
        case 4:  return 0.7071067811865475244f;
        case 5:  return 0.8314696123025452371f;
        case 6:  return 0.9238795325112867561f;
        case 7:  return 0.9807852804032304491f;
        case 8:  return 1.0f;
        case 9:  return 0.9807852804032304491f;
        case 10: return 0.9238795325112867561f;
        case 11: return 0.8314696123025452371f;
        case 12: return 0.7071067811865475244f;
        case 13: return 0.5555702330196022248f;
        case 14: return 0.3826834323650897717f;
        default: return 0.1950903220161282678f;
    }
}

__device__ __forceinline__ constexpr int brev(int p, int nb) {
    int r = 0;
    for (int i = 0; i < nb; i++) { r = (r << 1) | (p & 1); p >>= 1; }
    return r;
}

// Fully-unrolled radix-2 DIF FFT, size N (<=32). Natural input; output
// bit-reversed: reg p = X[brev(p, log2 N)]. Forward kernel e^{-i...}.
template<int N>
__device__ __forceinline__ void fft_dif(float* __restrict__ xr,
                                        float* __restrict__ xi) {
#pragma unroll
    for (int m = N / 2; m >= 1; m >>= 1) {
#pragma unroll
        for (int g = 0; g < N; g += 2 * m) {
#pragma unroll
            for (int j = 0; j < m; j++) {
                int a = g + j, b = g + j + m;
                float ur = xr[a], ui = xi[a];
                float vr = xr[b], vi = xi[b];
                xr[a] = ur + vr;
                xi[a] = ui + vi;
                float dr = ur - vr, di = ui - vi;
                float wc = c32(j * 16 / m);   // W_{2m}^j
                float ws = s32(j * 16 / m);
                xr[b] = dr * wc + di * ws;    // (dr+i di)*(wc - i ws)
                xi[b] = di * wc - dr * ws;
            }
        }
    }
}

// Stage-1 twiddle + transposed store. Rows t and t+16, twiddle bases w0, w1.
// Powers built in 4 chunks of 4 (depth ~6 instead of 15).
__device__ __forceinline__ void tw_transpose(float2* __restrict__ S,
                                             const float ar[2][16],
                                             const float ai[2][16],
                                             float2 w0, float2 w1, int t) {
    float2 w0_4 = cmulf(cmulf(w0, w0), cmulf(w0, w0));
    float2 w1_4 = cmulf(cmulf(w1, w1), cmulf(w1, w1));
    float2 base0 = make_float2(1.0f, 0.0f);
    float2 base1 = make_float2(1.0f, 0.0f);
#pragma unroll
    for (int a = 0; a < 4; a++) {
        float2 p0 = base0, p1 = base1;
#pragma unroll
        for (int c = 0; c < 4; c++) {
            int k2 = 4 * a + c;
            int pos = brev(k2, 4);
            S[t * 17 + k2] = make_float2(ar[0][pos] * p0.x - ai[0][pos] * p0.y,
                                         ar[0][pos] * p0.y + ai[0][pos] * p0.x);
            S[(t + 16) * 17 + k2] = make_float2(ar[1][pos] * p1.x - ai[1][pos] * p1.y,
                                                ar[1][pos] * p1.y + ai[1][pos] * p1.x);
            if (c < 3) { p0 = cmulf(p0, w0); p1 = cmulf(p1, w1); }
        }
        if (a < 3) { base0 = cmulf(base0, w0_4); base1 = cmulf(base1, w1_4); }
    }
}

__global__ void __launch_bounds__(THREADS, 9)
fft_conv_kernel(const float* __restrict__ x, const float* __restrict__ w,
                float* __restrict__ out) {
    __shared__ float2 sX[NFB][SBUF];
    __shared__ float sM[NW];

    int tid = threadIdx.x;
    int f = tid >> 4;       // FFT within block
    int t = tid & 15;       // lane within FFT
    float2* S = sX[f];

    // Twiddle bases: b0 = W^t, b1 = W^{t+16}, W = e^{-2pi i/512}.
    float2 b0, b1;
    sincospif(-(float)t * (1.0f / 256.0f), &b0.y, &b0.x);
    {
        const float wsr = 0.9807852804032304491f;    // cos(2pi*16/512)
        const float wsi = -0.1950903220161282678f;   // -sin(2pi*16/512)
        b1 = make_float2(b0.x * wsr - b0.y * wsi, b0.x * wsi + b0.y * wsr);
    }

    // ---- fused M (group f==0 computes all 512 bins into sM) ----
    // H(t+16m) = DFT32_m of zero-padded v[n] = w[n] * b0^n (n < 8).
    if (f == 0) {
        float vr[32], vi[32];
        vr[0] = __ldg(w + 0);
        vi[0] = 0.0f;
        float pr = b0.x, pi = b0.y;
#pragma unroll
        for (int n = 1; n < 8; n++) {
            float wt = __ldg(w + n);
            vr[n] = wt * pr;
            vi[n] = wt * pi;
            if (n < 7) {
                float nr = pr * b0.x - pi * b0.y;
                float ni = pr * b0.y + pi * b0.x;
                pr = nr; pi = ni;
            }
        }
#pragma unroll
        for (int n = 8; n < 32; n++) { vr[n] = 0.0f; vi[n] = 0.0f; }
        fft_dif<32>(vr, vi);             // reg p = H[t + 16*brev(p,5)]
#pragma unroll
        for (int p = 0; p < 32; p++) {
            float pw = vr[p] * vr[p] + vi[p] * vi[p];    // |H|^2
            sM[t + 16 * brev(p, 5)] = 1.0f / (pw * pw * (float)NW);
        }
    }
    __syncthreads();

    int row0 = (blockIdx.x * NFB + f) * 2;
    const float* x0 = x + row0 * NW;
    const float* x1 = x0 + NW;

    // ---- pass 0 (forward), stage 1: FFT16 over n2, n = t + 16b + 32n2 ----
    float ar[2][16], ai[2][16];
#pragma unroll
    for (int b = 0; b < 2; b++)
#pragma unroll
        for (int n2 = 0; n2 < 16; n2++) {
            int n = t + 16 * b + 32 * n2;
            ar[b][n2] = __ldg(x0 + n);
            ai[b][n2] = __ldg(x1 + n);
        }
    fft_dif<16>(ar[0], ai[0]);
    fft_dif<16>(ar[1], ai[1]);
    tw_transpose(S, ar, ai, b0, b1, t);
    __syncwarp();

    float cr[32], ci[32];
#pragma unroll
    for (int n1 = 0; n1 < 32; n1++) {
        float2 v = S[n1 * 17 + t];
        cr[n1] = v.x;
        ci[n1] = v.y;
    }
    __syncwarp();

    fft_dif<32>(cr, ci);                 // reg p = X[t + 16*brev(p,5)]

    // ---- M multiply + conjugate, stage g[k] through S ----
#pragma unroll
    for (int p = 0; p < 32; p++) {
        int k = t + 16 * brev(p, 5);
        float m = sM[k];
        S[k] = make_float2(cr[p] * m, -ci[p] * m);
    }
    __syncwarp();

    // ---- pass 1 (forward pipeline on g; conj trick), stage 1 input ----
#pragma unroll
    for (int b = 0; b < 2; b++)
#pragma unroll
        for (int n2 = 0; n2 < 16; n2++) {
            float2 v = S[t + 16 * b + 32 * n2];
            ar[b][n2] = v.x;
            ai[b][n2] = v.y;
        }
    __syncwarp();

    fft_dif<16>(ar[0], ai[0]);
    fft_dif<16>(ar[1], ai[1]);
    tw_transpose(S, ar, ai, b0, b1, t);
    __syncwarp();

#pragma unroll
    for (int n1 = 0; n1 < 32; n1++) {
        float2 v = S[n1 * 17 + t];
        cr[n1] = v.x;
        ci[n1] = v.y;
    }

    fft_dif<32>(cr, ci);                 // reg p = Ghat[n = t + 16*brev(p,5)]

    // y = conj(Ghat) (1/512 folded into M): re -> row0, -im -> row1.
    float* o0 = out + row0 * NW;
    float* o1 = o0 + NW;
#pragma unroll
    for (int p = 0; p < 32; p++) {
        int n = t + 16 * brev(p, 5);
        o0[n] = cr[p];
        o1[n] = -ci[p];
    }
}

extern "C" void kernel_launch(void* const* d_in, const int* in_sizes, int n_in,
                              void* d_out, int out_size) {
    const float* x = (const float*)d_in[0];
    const float* w = (const float*)d_in[1];
    if (n_in >= 2 && in_sizes[0] < in_sizes[1]) {   // defensive: x is the big one
        const float* t = x; x = w; w = t;
    }
    float* out = (float*)d_out;

    int rows = out_size / NW;          // 16384
    int blocks = rows / (2 * NFB);     // 2048 (8 rows per block)
    fft_conv_kernel<<<blocks, THREADS>>>(x, w, out);
}

// round 10
// speedup vs baseline: 1.3840x; 1.3840x over previous
#include <cuda_runtime.h>

// DeconvDft2dLayer == per-row 512-pt circular deconvolution:
//   y[row,:] = ifft( M(k) * fft(x[row,:]) ),  M(k) = 1/|H(k)|^4 (real),
//   H(k) = sum_{n=0}^{7} w[n] e^{-2pi i k n/512}.
// Two real rows packed per complex FFT (M real => exact).
// 512 = 16 x 32: 16 threads/FFT, 32 complex elems/thread, ONE smem
// transpose per direction, warp-synchronous. Inverse via conj trick.
// M fused at kernel top (zero live regs there): thread tid computes bins
// tid+64j via DFT8 of w[n]*e^{-2pi i tid n/512} into sM. Single launch.

#define NW 512
#define NFB 4                    // FFTs per block
#define THREADS 64               // 16 threads per FFT
#define SROW 17                  // padded row (float2) for conflict-free transpose
#define SBUF (32 * SROW)         // 544 float2 per FFT

// cos/sin(2*pi*j/32), j = 0..15 (compile-time switch).
__device__ __forceinline__ constexpr float c32(int j) {
    switch (j) {
        case 0:  return 1.0f;
        case 1:  return 0.9807852804032304491f;
        case 2:  return 0.9238795325112867561f;
        case 3:  return 0.8314696123025452371f;
        case 4:  return 0.7071067811865475244f;
        case 5:  return 0.5555702330196022248f;
        case 6:  return 0.3826834323650897717f;
        case 7:  return 0.1950903220161282678f;
        case 8:  return 0.0f;
        case 9:  return -0.1950903220161282678f;
        case 10: return -0.3826834323650897717f;
        case 11: return -0.5555702330196022248f;
        case 12: return -0.7071067811865475244f;
        case 13: return -0.8314696123025452371f;
        case 14: return -0.9238795325112867561f;
        default: return -0.9807852804032304491f;
    }
}
__device__ __forceinline__ constexpr float s32(int j) {
    switch (j) {
        case 0:  return 0.0f;
        case 1:  return 0.1950903220161282678f;
        case 2:  return 0.3826834323650897717f;
        case 3:  return 0.5555702330196022248f;
        case 4:  return 0.7071067811865475244f;
        case 5:  return 0.8314696123025452371f;
        case 6:  return 0.9238795325112867561f;
        case 7:  return 0.9807852804032304491f;
        case 8:  return 1.0f;
        case 9:  return 0.9807852804032304491f;
        case 10: return 0.9238795325112867561f;
        case 11: return 0.8314696123025452371f;
        case 12: return 0.7071067811865475244f;
        case 13: return 0.5555702330196022248f;
        case 14: return 0.3826834323650897717f;
        default: return 0.1950903220161282678f;
    }
}

__device__ __forceinline__ constexpr int brev(int p, int nb) {
    int r = 0;
    for (int i = 0; i < nb; i++) { r = (r << 1) | (p & 1); p >>= 1; }
    return r;
}

// Fully-unrolled radix-2 DIF FFT, size N (<=32). Natural-order input;
// output bit-reversed: reg p = X[brev(p, log2 N)]. Forward kernel e^{-i...}.
template<int N>
__device__ __forceinline__ void fft_dif(float* __restrict__ xr,
                                        float* __restrict__ xi) {
#pragma unroll
    for (int m = N / 2; m >= 1; m >>= 1) {
#pragma unroll
        for (int g = 0; g < N; g += 2 * m) {
#pragma unroll
            for (int j = 0; j < m; j++) {
                int a = g + j, b = g + j + m;
                float ur = xr[a], ui = xi[a];
                float vr = xr[b], vi = xi[b];
                xr[a] = ur + vr;
                xi[a] = ui + vi;
                float dr = ur - vr, di = ui - vi;
                float wc = c32(j * 16 / m);   // W_{2m}^j = e^{-2pi i j/(2m)}
                float ws = s32(j * 16 / m);
                xr[b] = dr * wc + di * ws;    // (dr+i di)*(wc - i ws)
                xi[b] = di * wc - dr * ws;
            }
        }
    }
}

__global__ void __launch_bounds__(THREADS)
fft_conv_kernel(const float* __restrict__ x, const float* __restrict__ w,
                float* __restrict__ out) {
    __shared__ float2 sX[NFB][SBUF];
    __shared__ float sM[NW];

    int tid = threadIdx.x;
    int f = tid >> 4;       // FFT within block
    int t = tid & 15;       // lane within FFT (n1 mod 16 / k2)
    float2* S = sX[f];

    // ---- fused M at kernel top (nothing live yet): bins tid + 64j ----
    // H(tid+64j) = DFT8_j( w[n] * e^{-2pi i tid n/512} ), fft_dif<8> output
    // is bit-reversed so bin j lands at reg brev(j,3).
    {
        float2 wu;
        sincospif(-(float)tid * (1.0f / 256.0f), &wu.y, &wu.x);
        float vr[8], vi[8];
        vr[0] = __ldg(w + 0);
        vi[0] = 0.0f;
        float pr = wu.x, pi = wu.y;
#pragma unroll
        for (int n = 1; n < 8; n++) {
            float wt = __ldg(w + n);
            vr[n] = wt * pr;
            vi[n] = wt * pi;
            if (n < 7) {
                float nr = pr * wu.x - pi * wu.y;
                float ni = pr * wu.y + pi * wu.x;
                pr = nr; pi = ni;
            }
        }
        fft_dif<8>(vr, vi);              // reg p = H[tid + 64*brev(p,3)]
#pragma unroll
        for (int p = 0; p < 8; p++) {
            float pw = vr[p] * vr[p] + vi[p] * vi[p];    // |H|^2
            sM[tid + 64 * brev(p, 3)] = 1.0f / (pw * pw * (float)NW);
        }
    }
    __syncthreads();   // sM ready (replaces the old preload sync)

    long long row0 = ((long long)blockIdx.x * NFB + f) * 2;
    const float* x0 = x + row0 * NW;
    const float* x1 = x0 + NW;

    // Twiddle bases: b0 = W^t, b1 = W^{t+16}, W = e^{-2pi i/512}.
    float b0r, b0i;
    sincospif(-(float)t * (1.0f / 256.0f), &b0i, &b0r);
    const float wsr = 0.9807852804032304491f;   // cos(pi/16)
    const float wsi = -0.1950903220161282678f;  // -sin(pi/16): e^{-2pi i 16/512}
    float b1r = b0r * wsr - b0i * wsi;
    float b1i = b0r * wsi + b0i * wsr;

    // Load: group b holds x[n], n = t + 16b + 32*n2 (n2 natural).
    float ar[2][16], ai[2][16];
#pragma unroll
    for (int b = 0; b < 2; b++)
#pragma unroll
        for (int n2 = 0; n2 < 16; n2++) {
            int n = t + 16 * b + 32 * n2;
            ar[b][n2] = __ldg(x0 + n);
            ai[b][n2] = __ldg(x1 + n);
        }

    float cr[32], ci[32];

    // ======== two passes: pass 0 = forward, pass 1 = inverse (conj trick) ====
#pragma unroll
    for (int pass = 0; pass < 2; pass++) {
        // Stage 1: FFT16 over n2 for n1 = t and n1 = t+16.
        fft_dif<16>(ar[0], ai[0]);
        fft_dif<16>(ar[1], ai[1]);
        // ar[b][p] = A[n1 = t+16b][k2 = brev(p,4)]

        // Twiddle by W^{n1*k2} (running products, natural k2 order) and
        // transpose-write S[n1][k2].
        {
            float p0r = 1.0f, p0i = 0.0f, p1r = 1.0f, p1i = 0.0f;
#pragma unroll
            for (int k2 = 0; k2 < 16; k2++) {
                if (k2) {
                    float n0r = p0r * b0r - p0i * b0i;
                    float n0i = p0r * b0i + p0i * b0r;
                    p0r = n0r; p0i = n0i;
                    float n1r = p1r * b1r - p1i * b1i;
                    float n1i = p1r * b1i + p1i * b1r;
                    p1r = n1r; p1i = n1i;
                }
                int pos = brev(k2, 4);
                S[t * SROW + k2] = make_float2(
                    ar[0][pos] * p0r - ai[0][pos] * p0i,
                    ar[0][pos] * p0i + ai[0][pos] * p0r);
                S[(t + 16) * SROW + k2] = make_float2(
                    ar[1][pos] * p1r - ai[1][pos] * p1i,
                    ar[1][pos] * p1i + ai[1][pos] * p1r);
            }
        }
        __syncwarp();

        // Transpose-read: natural n1 for this thread's k2 = t.
#pragma unroll
        for (int n1 = 0; n1 < 32; n1++) {
            float2 v = S[n1 * SROW + t];
            cr[n1] = v.x;
            ci[n1] = v.y;
        }
        __syncwarp();   // buffer reusable next pass

        // Stage 2: FFT32 over n1. cr[p] = X[t + 16*brev(p,5)].
        fft_dif<32>(cr, ci);

        if (pass == 0) {
            // Spectrum multiply by real M, conjugate, and permute into the
            // stage-1 register layout for the inverse pass.
#pragma unroll
            for (int b = 0; b < 2; b++)
#pragma unroll
                for (int n2 = 0; n2 < 16; n2++) {
                    int p = 16 * b + brev(n2, 4);
                    float m = sM[t + 32 * n2 + 16 * b];
                    ar[b][n2] = cr[p] * m;
                    ai[b][n2] = -ci[p] * m;
                }
        }
    }

    // y = conj(Z)/512 (1/512 folded into M): re -> row0, -im -> row1.
    float* o0 = out + row0 * NW;
    float* o1 = o0 + NW;
#pragma unroll
    for (int p = 0; p < 32; p++) {
        int m = t + 16 * brev(p, 5);
        o0[m] = cr[p];
        o1[m] = -ci[p];
    }
}

extern "C" void kernel_launch(void* const* d_in, const int* in_sizes, int n_in,
                              void* d_out, int out_size) {
    const float* x = (const float*)d_in[0];
    const float* w = (const float*)d_in[1];
    if (n_in >= 2 && in_sizes[0] < in_sizes[1]) {   // defensive: x is the big one
        const float* t = x; x = w; w = t;
    }
    float* out = (float*)d_out;

    int rows = out_size / NW;          // 16384
    int blocks = rows / (2 * NFB);     // 2048 (8 rows per block)
    fft_conv_kernel<<<blocks, THREADS>>>(x, w, out);
}

// round 11
// speedup vs baseline: 1.4009x; 1.0122x over previous
#include <cuda_runtime.h>

// DeconvDft2dLayer == per-row 512-pt circular deconvolution:
//   y[row,:] = ifft( M(k) * fft(x[row,:]) ),  M(k) = 1/|H(k)|^4 (real),
//   H(k) = sum_{n=0}^{7} w[n] e^{-2pi i k n/512}.
// Two real rows packed per complex FFT (M real => exact).
// 512 = 16 x 32: 16 threads/FFT, one smem transpose per direction.
// Inverse via conj trick reuses the forward pipeline; the inter-pass
// spectrum permute is staged through the (idle) smem buffer to keep the
// live register set at ~64 data regs (no cap, no spills).
// Warp-synchronous: zero block-wide barriers in the FFT kernel.

#define NW 512
#define NFB 4                    // FFTs per block (8 rows)
#define THREADS 64               // 16 threads per FFT
#define SROW 17                  // padded row (float2) for conflict-free transpose
#define SBUF (32 * SROW)         // 544 float2 per FFT

__device__ float d_M[NW];        // M(k)/512  (ifft 1/N folded in)

__global__ void compute_M_kernel(const float* __restrict__ w) {
    int k = threadIdx.x;
    float hr = 0.0f, hi = 0.0f;
#pragma unroll
    for (int n = 0; n < 8; n++) {
        int t = (k * n) & (NW - 1);          // exact integer phase
        float s, c;
        sincospif(-(float)t * (2.0f / NW), &s, &c);
        hr = fmaf(w[n], c, hr);
        hi = fmaf(w[n], s, hi);
    }
    float p = hr * hr + hi * hi;             // |H|^2
    d_M[k] = 1.0f / (p * p * (float)NW);
}

__device__ __forceinline__ float2 cmulf(float2 a, float2 b) {
    return make_float2(a.x * b.x - a.y * b.y, a.x * b.y + a.y * b.x);
}

// cos/sin(2*pi*j/32), j = 0..15 (compile-time switch).
__device__ __forceinline__ constexpr float c32(int j) {
    switch (j) {
        case 0:  return 1.0f;
        case 1:  return 0.9807852804032304491f;
        case 2:  return 0.9238795325112867561f;
        case 3:  return 0.8314696123025452371f;
        case 4:  return 0.7071067811865475244f;
        case 5:  return 0.5555702330196022248f;
        case 6:  return 0.3826834323650897717f;
        case 7:  return 0.1950903220161282678f;
        case 8:  return 0.0f;
        case 9:  return -0.1950903220161282678f;
        case 10: return -0.3826834323650897717f;
        case 11: return -0.5555702330196022248f;
        case 12: return -0.7071067811865475244f;
        case 13: return -0.8314696123025452371f;
        case 14: return -0.9238795325112867561f;
        default: return -0.9807852804032304491f;
    }
}
__device__ __forceinline__ constexpr float s32(int j) {
    switch (j) {
        case 0:  return 0.0f;
        case 1:  return 0.1950903220161282678f;
        case 2:  return 0.3826834323650897717f;
        case 3:  return 0.5555702330196022248f;
        case 4:  return 0.7071067811865475244f;
        case 5:  return 0.8314696123025452371f;
        case 6:  return 0.9238795325112867561f;
        case 7:  return 0.9807852804032304491f;
        case 8:  return 1.0f;
        case 9:  return 0.9807852804032304491f;
        case 10: return 0.9238795325112867561f;
        case 11: return 0.8314696123025452371f;
        case 12: return 0.7071067811865475244f;
        case 13: return 0.5555702330196022248f;
        case 14: return 0.3826834323650897717f;
        default: return 0.1950903220161282678f;
    }
}

__device__ __forceinline__ constexpr int brev(int p, int nb) {
    int r = 0;
    for (int i = 0; i < nb; i++) { r = (r << 1) | (p & 1); p >>= 1; }
    return r;
}

// Fully-unrolled radix-2 DIF FFT, size N (<=32). Natural input; output
// bit-reversed: reg p = X[brev(p, log2 N)]. Forward kernel e^{-i...}.
template<int N>
__device__ __forceinline__ void fft_dif(float* __restrict__ xr,
                                        float* __restrict__ xi) {
#pragma unroll
    for (int m = N / 2; m >= 1; m >>= 1) {
#pragma unroll
        for (int g = 0; g < N; g += 2 * m) {
#pragma unroll
            for (int j = 0; j < m; j++) {
                int a = g + j, b = g + j + m;
                float ur = xr[a], ui = xi[a];
                float vr = xr[b], vi = xi[b];
                xr[a] = ur + vr;
                xi[a] = ui + vi;
                float dr = ur - vr, di = ui - vi;
                float wc = c32(j * 16 / m);   // W_{2m}^j = e^{-2pi i j/(2m)}
                float ws = s32(j * 16 / m);
                xr[b] = dr * wc + di * ws;    // (dr+i di)*(wc - i ws)
                xi[b] = di * wc - dr * ws;
            }
        }
    }
}

// Stage-1 twiddle + transposed store: rows t and t+16, bases w0, w1.
// Powers built in 4 chunks of 4 (dependency depth ~6 instead of 15).
__device__ __forceinline__ void tw_transpose(float2* __restrict__ S,
                                             const float ar[2][16],
                                             const float ai[2][16],
                                             float2 w0, float2 w1, int t) {
    float2 w0sq = cmulf(w0, w0);
    float2 w1sq = cmulf(w1, w1);
    float2 w0_4 = cmulf(w0sq, w0sq);
    float2 w1_4 = cmulf(w1sq, w1sq);
    float2 base0 = make_float2(1.0f, 0.0f);
    float2 base1 = make_float2(1.0f, 0.0f);
#pragma unroll
    for (int a = 0; a < 4; a++) {
        float2 p0 = base0, p1 = base1;
#pragma unroll
        for (int c = 0; c < 4; c++) {
            int k2 = 4 * a + c;
            int pos = brev(k2, 4);
            S[t * SROW + k2] = make_float2(ar[0][pos] * p0.x - ai[0][pos] * p0.y,
                                           ar[0][pos] * p0.y + ai[0][pos] * p0.x);
            S[(t + 16) * SROW + k2] = make_float2(ar[1][pos] * p1.x - ai[1][pos] * p1.y,
                                                  ar[1][pos] * p1.y + ai[1][pos] * p1.x);
            if (c < 3) { p0 = cmulf(p0, w0); p1 = cmulf(p1, w1); }
        }
        if (a < 3) { base0 = cmulf(base0, w0_4); base1 = cmulf(base1, w1_4); }
    }
}

__global__ void __launch_bounds__(THREADS)
fft_conv_kernel(const float* __restrict__ x, float* __restrict__ out) {
    __shared__ float2 sX[NFB][SBUF];

    int tid = threadIdx.x;
    int f = tid >> 4;       // FFT within block
    int t = tid & 15;       // lane within FFT (n1 mod 16 / k2)
    float2* S = sX[f];

    long long row0 = ((long long)blockIdx.x * NFB + f) * 2;
    const float* x0 = x + row0 * NW;
    const float* x1 = x0 + NW;

    // Twiddle bases: b0 = W^t, b1 = W^{t+16}, W = e^{-2pi i/512}.
    float2 b0, b1;
    sincospif(-(float)t * (1.0f / 256.0f), &b0.y, &b0.x);
    {
        const float wsr = 0.9807852804032304491f;    // cos(2pi*16/512)
        const float wsi = -0.1950903220161282678f;   // -sin(2pi*16/512)
        b1 = make_float2(b0.x * wsr - b0.y * wsi, b0.x * wsi + b0.y * wsr);
    }

    // ---- pass 0 (forward), stage 1: FFT16 over n2; n = t + 16b + 32n2 ----
    {
        float ar[2][16], ai[2][16];
#pragma unroll
        for (int b = 0; b < 2; b++)
#pragma unroll
            for (int n2 = 0; n2 < 16; n2++) {
                int n = t + 16 * b + 32 * n2;
                ar[b][n2] = __ldg(x0 + n);
                ai[b][n2] = __ldg(x1 + n);
            }
        fft_dif<16>(ar[0], ai[0]);
        fft_dif<16>(ar[1], ai[1]);
        tw_transpose(S, ar, ai, b0, b1, t);
    }
    __syncwarp();

    // ---- pass 0, stage 2: FFT32 over n1 for k2 = t ----
    {
        float cr[32], ci[32];
#pragma unroll
        for (int n1 = 0; n1 < 32; n1++) {
            float2 v = S[n1 * SROW + t];
            cr[n1] = v.x;
            ci[n1] = v.y;
        }
        __syncwarp();           // all reads done before overwrite below

        fft_dif<32>(cr, ci);    // reg p = X[t + 16*brev(p,5)]

        // Stage g[k] = conj(M*X[k]) through S in pass-1 input layout.
#pragma unroll
        for (int p = 0; p < 32; p++) {
            int k = t + 16 * brev(p, 5);
            float m = __ldg(&d_M[k]);
            S[k] = make_float2(cr[p] * m, -ci[p] * m);
        }
    }
    __syncwarp();

    // ---- pass 1 (forward pipeline on g; conj trick), stage 1 ----
    {
        float ar[2][16], ai[2][16];
#pragma unroll
        for (int b = 0; b < 2; b++)
#pragma unroll
            for (int n2 = 0; n2 < 16; n2++) {
                float2 v = S[t + 16 * b + 32 * n2];
                ar[b][n2] = v.x;
                ai[b][n2] = v.y;
            }
        __syncwarp();           // reads done before transpose store

        fft_dif<16>(ar[0], ai[0]);
        fft_dif<16>(ar[1], ai[1]);
        tw_transpose(S, ar, ai, b0, b1, t);
    }
    __syncwarp();

    // ---- pass 1, stage 2 + output ----
    {
        float cr[32], ci[32];
#pragma unroll
        for (int n1 = 0; n1 < 32; n1++) {
            float2 v = S[n1 * SROW + t];
            cr[n1] = v.x;
            ci[n1] = v.y;
        }

        fft_dif<32>(cr, ci);    // reg p = Ghat[n = t + 16*brev(p,5)]

        // y = conj(Ghat) (1/512 folded into M): re -> row0, -im -> row1.
        float* o0 = out + row0 * NW;
        float* o1 = o0 + NW;
#pragma unroll
        for (int p = 0; p < 32; p++) {
            int n = t + 16 * brev(p, 5);
            o0[n] = cr[p];
            o1[n] = -ci[p];
        }
    }
}

extern "C" void kernel_launch(void* const* d_in, const int* in_sizes, int n_in,
                              void* d_out, int out_size) {
    const float* x = (const float*)d_in[0];
    const float* w = (const float*)d_in[1];
    if (n_in >= 2 && in_sizes[0] < in_sizes[1]) {   // defensive: x is the big one
        const float* t = x; x = w; w = t;
    }
    float* out = (float*)d_out;

    compute_M_kernel<<<1, NW>>>(w);

    int rows = out_size / NW;          // 16384
    int blocks = rows / (2 * NFB);     // 2048 (8 rows per block)
    fft_conv_kernel<<<blocks, THREADS>>>(x, out);
}